// round 1
// baseline (speedup 1.0000x reference)
#include <cuda_runtime.h>
#include <cstdint>
#include <cstddef>

#define N_NODES 50000
#define N_EDGES 800000
#define EDGE_F 96
#define NODE_F 256
#define GLOB_F 64
#define HIDDEN 1024
#define MLP_IN 608
#define CAP 128

// ---------------- scratch (static device globals; no allocations) ------------
__device__ int   g_cnt[N_NODES];
__device__ int   g_bucket[N_NODES * CAP];                 // 25.6 MB
__device__ float g_h[(size_t)N_NODES * MLP_IN];           // 121.6 MB (tf32-rounded)
__device__ float g_hid[(size_t)N_NODES * HIDDEN];         // 204.8 MB (tf32-rounded)
__device__ float g_w1[MLP_IN * HIDDEN];                   // tf32-rounded W1
__device__ float g_w2[HIDDEN * NODE_F];                   // tf32-rounded W2

__device__ __forceinline__ float tf32r(float x) {
    unsigned u;
    asm("cvt.rna.tf32.f32 %0, %1;" : "=r"(u) : "f"(x));
    return __uint_as_float(u);
}

// ---------------- prep kernels ----------------------------------------------
__global__ void k_zero() {
    int i = blockIdx.x * blockDim.x + threadIdx.x;
    if (i < N_NODES) g_cnt[i] = 0;
}

__global__ void k_scatter(const int* __restrict__ col) {
    int e = blockIdx.x * blockDim.x + threadIdx.x;
    if (e >= N_EDGES) return;
    int c = col[e];
    int p = atomicAdd(&g_cnt[c], 1);
    if (p < CAP) g_bucket[c * CAP + p] = e;
}

__global__ void k_cvtw(const float* __restrict__ W1, const float* __restrict__ W2) {
    int i = blockIdx.x * blockDim.x + threadIdx.x;
    const int n1 = MLP_IN * HIDDEN;
    const int nt = n1 + HIDDEN * NODE_F;
    if (i < n1)      g_w1[i]      = tf32r(W1[i]);
    else if (i < nt) g_w2[i - n1] = tf32r(W2[i - n1]);
}

// warp-per-node gather-reduce; assembles the full tf32-rounded h row
__global__ void k_gather(const float* __restrict__ x, const float* __restrict__ ea,
                         const float* __restrict__ u, const int* __restrict__ batch) {
    int node = blockIdx.x * 8 + (threadIdx.x >> 5);
    if (node >= N_NODES) return;
    int lane = threadIdx.x & 31;
    int deg = g_cnt[node];
    if (deg > CAP) deg = CAP;
    const float NEG = __int_as_float(0xff800000);
    float s0 = 0.f, s1 = 0.f, s2 = 0.f;
    float m0 = NEG, m1 = NEG, m2 = NEG;
    const int* bk = g_bucket + node * CAP;
    for (int j = 0; j < deg; j++) {
        const float* r = ea + (size_t)bk[j] * EDGE_F;
        float v0 = r[lane], v1 = r[lane + 32], v2 = r[lane + 64];
        s0 += v0; m0 = fmaxf(m0, v0);
        s1 += v1; m1 = fmaxf(m1, v1);
        s2 += v2; m2 = fmaxf(m2, v2);
    }
    if (deg == 0) { m0 = 0.f; m1 = 0.f; m2 = 0.f; }
    float inv = deg ? 1.f / (float)deg : 0.f;

    float* h = g_h + (size_t)node * MLP_IN;
    const float* xr = x + (size_t)node * NODE_F;
#pragma unroll
    for (int i = 0; i < 8; i++) h[lane + 32 * i] = tf32r(xr[lane + 32 * i]);
    h[256 + lane] = tf32r(s0);  h[288 + lane] = tf32r(s1);  h[320 + lane] = tf32r(s2);
    h[352 + lane] = tf32r(m0);  h[384 + lane] = tf32r(m1);  h[416 + lane] = tf32r(m2);
    h[448 + lane] = tf32r(s0 * inv); h[480 + lane] = tf32r(s1 * inv); h[512 + lane] = tf32r(s2 * inv);
    int g = batch[node];
    h[544 + lane] = tf32r(u[g * GLOB_F + lane]);
    h[576 + lane] = tf32r(u[g * GLOB_F + 32 + lane]);
}

// ---------------- tf32 GEMM (mma.sync m16n8k8, cp.async double-buffered) -----
#define BM 128
#define BN 128
#define BK 32
#define SA 36      // A smem stride (floats) -> conflict-free fragment LDS
#define SB 136     // B smem stride (floats) -> conflict-free fragment LDS
#define ASZ (BM * SA)
#define BSZ (BK * SB)
#define STG (ASZ + BSZ)

__device__ __forceinline__ void cp16(uint32_t dst, const void* src, int sz) {
    asm volatile("cp.async.cg.shared.global [%0], [%1], 16, %2;\n"
                 :: "r"(dst), "l"(src), "r"(sz));
}

template <bool FIRST>
__global__ void __launch_bounds__(256)
k_gemm(const float* __restrict__ A, const float* __restrict__ B,
       const float* __restrict__ bias, const float* __restrict__ resid,
       float* __restrict__ C, int M, int K, int N) {
    extern __shared__ float sm[];
    uint32_t smb = (uint32_t)__cvta_generic_to_shared(sm);
    int tid = threadIdx.x;
    int bm = blockIdx.y * BM;
    int bn = blockIdx.x * BN;
    int KT = K / BK;

    auto load = [&](int st, int kb) {
        uint32_t base = smb + st * STG * 4;
#pragma unroll
        for (int i = 0; i < 4; i++) {           // A tile: 128 x 32
            int id = tid + i * 256;
            int r = id >> 3, cc = id & 7;
            int gr = bm + r;
            int src_r = (gr < M) ? gr : (M - 1);
            const float* src = A + (size_t)src_r * K + kb * BK + cc * 4;
            cp16(base + (r * SA + cc * 4) * 4, src, (gr < M) ? 16 : 0);
        }
        uint32_t bbase = base + ASZ * 4;
#pragma unroll
        for (int i = 0; i < 4; i++) {           // B tile: 32 x 128
            int id = tid + i * 256;
            int r = id >> 5, cc = id & 31;
            const float* src = B + (size_t)(kb * BK + r) * N + bn + cc * 4;
            cp16(bbase + (r * SB + cc * 4) * 4, src, 16);
        }
    };

    load(0, 0);
    asm volatile("cp.async.commit_group;\n");

    float acc[4][4][4];
#pragma unroll
    for (int a = 0; a < 4; a++)
#pragma unroll
        for (int b = 0; b < 4; b++)
#pragma unroll
            for (int c = 0; c < 4; c++) acc[a][b][c] = 0.f;

    int warp = tid >> 5, lane = tid & 31;
    int wm = (warp & 1) * 64, wn = (warp >> 1) * 32;
    int lr = lane >> 2, lc = lane & 3;

    for (int kt = 0; kt < KT; kt++) {
        if (kt + 1 < KT) load((kt + 1) & 1, kt + 1);
        asm volatile("cp.async.commit_group;\n");
        asm volatile("cp.async.wait_group 1;\n");
        __syncthreads();
        const float* a_s = sm + (kt & 1) * STG;
        const float* b_s = a_s + ASZ;
#pragma unroll
        for (int k0 = 0; k0 < BK; k0 += 8) {
            uint32_t af[4][4], bf[4][2];
#pragma unroll
            for (int mt = 0; mt < 4; mt++) {
                int r = wm + mt * 16 + lr;
                af[mt][0] = __float_as_uint(a_s[r * SA + k0 + lc]);
                af[mt][1] = __float_as_uint(a_s[(r + 8) * SA + k0 + lc]);
                af[mt][2] = __float_as_uint(a_s[r * SA + k0 + lc + 4]);
                af[mt][3] = __float_as_uint(a_s[(r + 8) * SA + k0 + lc + 4]);
            }
#pragma unroll
            for (int nt = 0; nt < 4; nt++) {
                int n = wn + nt * 8 + lr;
                bf[nt][0] = __float_as_uint(b_s[(k0 + lc) * SB + n]);
                bf[nt][1] = __float_as_uint(b_s[(k0 + lc + 4) * SB + n]);
            }
#pragma unroll
            for (int mt = 0; mt < 4; mt++)
#pragma unroll
                for (int nt = 0; nt < 4; nt++)
                    asm volatile(
                        "mma.sync.aligned.m16n8k8.row.col.f32.tf32.tf32.f32 "
                        "{%0,%1,%2,%3},{%4,%5,%6,%7},{%8,%9},{%0,%1,%2,%3};\n"
                        : "+f"(acc[mt][nt][0]), "+f"(acc[mt][nt][1]),
                          "+f"(acc[mt][nt][2]), "+f"(acc[mt][nt][3])
                        : "r"(af[mt][0]), "r"(af[mt][1]), "r"(af[mt][2]), "r"(af[mt][3]),
                          "r"(bf[nt][0]), "r"(bf[nt][1]));
        }
        __syncthreads();
    }

    // epilogue
#pragma unroll
    for (int mt = 0; mt < 4; mt++) {
        int rb = bm + wm + mt * 16 + lr;
#pragma unroll
        for (int nt = 0; nt < 4; nt++) {
            int cb = bn + wn + nt * 8 + 2 * lc;
#pragma unroll
            for (int i = 0; i < 4; i++) {
                int row = rb + ((i >> 1) << 3);
                int colI = cb + (i & 1);
                if (row < M) {
                    float v = acc[mt][nt][i] + bias[colI];
                    if (FIRST) {
                        v = fmaxf(v, 0.f);
                        v = tf32r(v);                       // pre-round for GEMM2
                    } else {
                        v += resid[(size_t)row * N + colI]; // residual +x
                    }
                    C[(size_t)row * N + colI] = v;
                }
            }
        }
    }
}

// ---------------- launch ------------------------------------------------------
extern "C" void kernel_launch(void* const* d_in, const int* in_sizes, int n_in,
                              void* d_out, int out_size) {
    const float* x  = (const float*)d_in[0];
    const float* ea = (const float*)d_in[1];
    const float* u  = (const float*)d_in[2];
    const float* W1 = (const float*)d_in[3];
    const float* b1 = (const float*)d_in[4];
    const float* W2 = (const float*)d_in[5];
    const float* b2 = (const float*)d_in[6];
    const int*   ei = (const int*)d_in[7];   // [2, N_EDGES] int32
    const int*   bt = (const int*)d_in[8];
    float* out = (float*)d_out;

    float *pH, *pHid, *pW1, *pW2;
    cudaGetSymbolAddress((void**)&pH, g_h);
    cudaGetSymbolAddress((void**)&pHid, g_hid);
    cudaGetSymbolAddress((void**)&pW1, g_w1);
    cudaGetSymbolAddress((void**)&pW2, g_w2);

    const int smem = 2 * STG * 4;   // 71680 B
    cudaFuncSetAttribute(k_gemm<true>,  cudaFuncAttributeMaxDynamicSharedMemorySize, smem);
    cudaFuncSetAttribute(k_gemm<false>, cudaFuncAttributeMaxDynamicSharedMemorySize, smem);

    k_zero<<<(N_NODES + 255) / 256, 256>>>();
    k_scatter<<<(N_EDGES + 255) / 256, 256>>>(ei + N_EDGES);
    k_cvtw<<<(MLP_IN * HIDDEN + HIDDEN * NODE_F + 255) / 256, 256>>>(W1, W2);
    k_gather<<<(N_NODES + 7) / 8, 256>>>(x, ea, u, bt);

    dim3 g1(HIDDEN / BN, (N_NODES + BM - 1) / BM);
    k_gemm<true><<<g1, 256, smem>>>(pH, pW1, b1, nullptr, pHid,
                                    N_NODES, MLP_IN, HIDDEN);
    dim3 g2(NODE_F / BN, (N_NODES + BM - 1) / BM);
    k_gemm<false><<<g2, 256, smem>>>(pHid, pW2, b2, x, out,
                                     N_NODES, HIDDEN, NODE_F);
}

// round 4
// speedup vs baseline: 1.0230x; 1.0230x over previous
#include <cuda_runtime.h>
#include <cstdint>
#include <cstddef>

#define N_NODES 50000
#define N_EDGES 800000
#define EDGE_F 96
#define NODE_F 256
#define GLOB_F 64
#define HIDDEN 1024
#define MLP_IN 608
#define CAP 128

// ---------------- scratch (static device globals; no allocations) ------------
__device__ int   g_cnt[N_NODES];
__device__ int   g_bucket[N_NODES * CAP];                 // 25.6 MB
__device__ float g_h[(size_t)N_NODES * MLP_IN];           // tf32-rounded
__device__ float g_hid[(size_t)N_NODES * HIDDEN];         // tf32-rounded
__device__ float g_w1[MLP_IN * HIDDEN];                   // tf32-rounded W1
__device__ float g_w2[HIDDEN * NODE_F];                   // tf32-rounded W2

__device__ __forceinline__ float tf32r(float x) {
    unsigned u;
    asm("cvt.rna.tf32.f32 %0, %1;" : "=r"(u) : "f"(x));
    return __uint_as_float(u);
}

// ---------------- prep kernels ----------------------------------------------
__global__ void k_zero() {
    int i = blockIdx.x * blockDim.x + threadIdx.x;
    if (i < N_NODES) g_cnt[i] = 0;
}

__global__ void k_scatter(const int* __restrict__ col) {
    int e = blockIdx.x * blockDim.x + threadIdx.x;
    if (e >= N_EDGES) return;
    int c = col[e];
    int p = atomicAdd(&g_cnt[c], 1);
    if (p < CAP) g_bucket[c * CAP + p] = e;
}

__global__ void k_cvtw(const float* __restrict__ W1, const float* __restrict__ W2) {
    int i = blockIdx.x * blockDim.x + threadIdx.x;
    const int n1 = MLP_IN * HIDDEN;
    const int nt = n1 + HIDDEN * NODE_F;
    if (i < n1)      g_w1[i]      = tf32r(W1[i]);
    else if (i < nt) g_w2[i - n1] = tf32r(W2[i - n1]);
}

// warp-per-node gather-reduce with 4-wide index prefetch
__global__ void k_gather(const float* __restrict__ x, const float* __restrict__ ea,
                         const float* __restrict__ u, const int* __restrict__ batch) {
    int node = blockIdx.x * 8 + (threadIdx.x >> 5);
    if (node >= N_NODES) return;
    int lane = threadIdx.x & 31;
    int deg = g_cnt[node];
    if (deg > CAP) deg = CAP;
    const float NEG = __int_as_float(0xff800000);
    float s0 = 0.f, s1 = 0.f, s2 = 0.f;
    float m0 = NEG, m1 = NEG, m2 = NEG;
    const int* bk = g_bucket + node * CAP;

    int j = 0;
    for (; j + 4 <= deg; j += 4) {
        int e0 = bk[j], e1 = bk[j + 1], e2 = bk[j + 2], e3 = bk[j + 3];
        const float* r0p = ea + (size_t)e0 * EDGE_F;
        const float* r1p = ea + (size_t)e1 * EDGE_F;
        const float* r2p = ea + (size_t)e2 * EDGE_F;
        const float* r3p = ea + (size_t)e3 * EDGE_F;
        float a0 = r0p[lane], a1 = r0p[lane + 32], a2 = r0p[lane + 64];
        float b0 = r1p[lane], b1 = r1p[lane + 32], b2 = r1p[lane + 64];
        float c0 = r2p[lane], c1 = r2p[lane + 32], c2 = r2p[lane + 64];
        float d0 = r3p[lane], d1 = r3p[lane + 32], d2 = r3p[lane + 64];
        s0 += a0 + b0 + c0 + d0;
        s1 += a1 + b1 + c1 + d1;
        s2 += a2 + b2 + c2 + d2;
        m0 = fmaxf(m0, fmaxf(fmaxf(a0, b0), fmaxf(c0, d0)));
        m1 = fmaxf(m1, fmaxf(fmaxf(a1, b1), fmaxf(c1, d1)));
        m2 = fmaxf(m2, fmaxf(fmaxf(a2, b2), fmaxf(c2, d2)));
    }
    for (; j < deg; j++) {
        const float* r = ea + (size_t)bk[j] * EDGE_F;
        float v0 = r[lane], v1 = r[lane + 32], v2 = r[lane + 64];
        s0 += v0; m0 = fmaxf(m0, v0);
        s1 += v1; m1 = fmaxf(m1, v1);
        s2 += v2; m2 = fmaxf(m2, v2);
    }
    if (deg == 0) { m0 = 0.f; m1 = 0.f; m2 = 0.f; }
    float inv = deg ? 1.f / (float)deg : 0.f;

    float* h = g_h + (size_t)node * MLP_IN;
    const float* xr = x + (size_t)node * NODE_F;
#pragma unroll
    for (int i = 0; i < 8; i++) h[lane + 32 * i] = tf32r(xr[lane + 32 * i]);
    h[256 + lane] = tf32r(s0);  h[288 + lane] = tf32r(s1);  h[320 + lane] = tf32r(s2);
    h[352 + lane] = tf32r(m0);  h[384 + lane] = tf32r(m1);  h[416 + lane] = tf32r(m2);
    h[448 + lane] = tf32r(s0 * inv); h[480 + lane] = tf32r(s1 * inv); h[512 + lane] = tf32r(s2 * inv);
    int g = batch[node];
    h[544 + lane] = tf32r(u[g * GLOB_F + lane]);
    h[576 + lane] = tf32r(u[g * GLOB_F + 32 + lane]);
}

// ---------------- tf32 GEMM (mma.sync m16n8k8, cp.async double-buffered) -----
#define BM 128
#define BN 128
#define BK 32
#define SA 36      // A smem stride (floats) -> conflict-free fragment LDS
#define SB 136     // B smem stride (floats) -> conflict-free fragment LDS
#define ASZ (BM * SA)
#define BSZ (BK * SB)
#define STG (ASZ + BSZ)

__device__ __forceinline__ void cp16(uint32_t dst, const void* src, int sz) {
    asm volatile("cp.async.cg.shared.global [%0], [%1], 16, %2;\n"
                 :: "r"(dst), "l"(src), "r"(sz));
}

template <bool FIRST>
__global__ void __launch_bounds__(256, 2)
k_gemm(const float* __restrict__ A, const float* __restrict__ B,
       const float* __restrict__ bias, const float* __restrict__ resid,
       float* __restrict__ C, int M, int K, int N) {
    extern __shared__ float sm[];
    uint32_t smb = (uint32_t)__cvta_generic_to_shared(sm);
    int tid = threadIdx.x;
    int bm = blockIdx.y * BM;
    int bn = blockIdx.x * BN;
    int KT = K / BK;

    auto load = [&](int st, int kb) {
        uint32_t base = smb + st * STG * 4;
#pragma unroll
        for (int i = 0; i < 4; i++) {           // A tile: 128 x 32
            int id = tid + i * 256;
            int r = id >> 3, cc = id & 7;
            int gr = bm + r;
            int src_r = (gr < M) ? gr : (M - 1);
            const float* src = A + (size_t)src_r * K + kb * BK + cc * 4;
            cp16(base + (r * SA + cc * 4) * 4, src, (gr < M) ? 16 : 0);
        }
        uint32_t bbase = base + ASZ * 4;
#pragma unroll
        for (int i = 0; i < 4; i++) {           // B tile: 32 x 128
            int id = tid + i * 256;
            int r = id >> 5, cc = id & 31;
            const float* src = B + (size_t)(kb * BK + r) * N + bn + cc * 4;
            cp16(bbase + (r * SB + cc * 4) * 4, src, 16);
        }
    };

    load(0, 0);
    asm volatile("cp.async.commit_group;\n");

    float acc[4][4][4];
#pragma unroll
    for (int a = 0; a < 4; a++)
#pragma unroll
        for (int b = 0; b < 4; b++)
#pragma unroll
            for (int c = 0; c < 4; c++) acc[a][b][c] = 0.f;

    int warp = tid >> 5, lane = tid & 31;
    int wm = (warp & 1) * 64, wn = (warp >> 1) * 32;
    int lr = lane >> 2, lc = lane & 3;

    for (int kt = 0; kt < KT; kt++) {
        if (kt + 1 < KT) load((kt + 1) & 1, kt + 1);
        asm volatile("cp.async.commit_group;\n");
        asm volatile("cp.async.wait_group 1;\n");
        __syncthreads();
        const float* a_s = sm + (kt & 1) * STG;
        const float* b_s = a_s + ASZ;
#pragma unroll
        for (int k0 = 0; k0 < BK; k0 += 8) {
            uint32_t af[4][4], bf[4][2];
#pragma unroll
            for (int mt = 0; mt < 4; mt++) {
                int r = wm + mt * 16 + lr;
                af[mt][0] = __float_as_uint(a_s[r * SA + k0 + lc]);
                af[mt][1] = __float_as_uint(a_s[(r + 8) * SA + k0 + lc]);
                af[mt][2] = __float_as_uint(a_s[r * SA + k0 + lc + 4]);
                af[mt][3] = __float_as_uint(a_s[(r + 8) * SA + k0 + lc + 4]);
            }
#pragma unroll
            for (int nt = 0; nt < 4; nt++) {
                int n = wn + nt * 8 + lr;
                bf[nt][0] = __float_as_uint(b_s[(k0 + lc) * SB + n]);
                bf[nt][1] = __float_as_uint(b_s[(k0 + lc + 4) * SB + n]);
            }
#pragma unroll
            for (int mt = 0; mt < 4; mt++)
#pragma unroll
                for (int nt = 0; nt < 4; nt++)
                    asm volatile(
                        "mma.sync.aligned.m16n8k8.row.col.f32.tf32.tf32.f32 "
                        "{%0,%1,%2,%3},{%4,%5,%6,%7},{%8,%9},{%0,%1,%2,%3};\n"
                        : "+f"(acc[mt][nt][0]), "+f"(acc[mt][nt][1]),
                          "+f"(acc[mt][nt][2]), "+f"(acc[mt][nt][3])
                        : "r"(af[mt][0]), "r"(af[mt][1]), "r"(af[mt][2]), "r"(af[mt][3]),
                          "r"(bf[nt][0]), "r"(bf[nt][1]));
        }
        __syncthreads();
    }

    // epilogue
#pragma unroll
    for (int mt = 0; mt < 4; mt++) {
        int rb = bm + wm + mt * 16 + lr;
#pragma unroll
        for (int nt = 0; nt < 4; nt++) {
            int cb = bn + wn + nt * 8 + 2 * lc;
#pragma unroll
            for (int i = 0; i < 4; i++) {
                int row = rb + ((i >> 1) << 3);
                int colI = cb + (i & 1);
                if (row < M) {
                    float v = acc[mt][nt][i] + bias[colI];
                    if (FIRST) {
                        v = fmaxf(v, 0.f);
                        v = tf32r(v);                       // pre-round for GEMM2
                    } else {
                        v += resid[(size_t)row * N + colI]; // residual +x
                    }
                    C[(size_t)row * N + colI] = v;
                }
            }
        }
    }
}

// ---------------- launch ------------------------------------------------------
extern "C" void kernel_launch(void* const* d_in, const int* in_sizes, int n_in,
                              void* d_out, int out_size) {
    const float* x  = (const float*)d_in[0];
    const float* ea = (const float*)d_in[1];
    const float* u  = (const float*)d_in[2];
    const float* W1 = (const float*)d_in[3];
    const float* b1 = (const float*)d_in[4];
    const float* W2 = (const float*)d_in[5];
    const float* b2 = (const float*)d_in[6];
    const int*   ei = (const int*)d_in[7];   // [2, N_EDGES] int32
    const int*   bt = (const int*)d_in[8];
    float* out = (float*)d_out;

    float *pH, *pHid, *pW1, *pW2;
    cudaGetSymbolAddress((void**)&pH, g_h);
    cudaGetSymbolAddress((void**)&pHid, g_hid);
    cudaGetSymbolAddress((void**)&pW1, g_w1);
    cudaGetSymbolAddress((void**)&pW2, g_w2);

    const int smem = 2 * STG * 4;   // 71680 B
    cudaFuncSetAttribute(k_gemm<true>,  cudaFuncAttributeMaxDynamicSharedMemorySize, smem);
    cudaFuncSetAttribute(k_gemm<false>, cudaFuncAttributeMaxDynamicSharedMemorySize, smem);

    k_zero<<<(N_NODES + 255) / 256, 256>>>();
    k_scatter<<<(N_EDGES + 255) / 256, 256>>>(ei + N_EDGES);
    k_cvtw<<<(MLP_IN * HIDDEN + HIDDEN * NODE_F + 255) / 256, 256>>>(W1, W2);
    k_gather<<<(N_NODES + 7) / 8, 256>>>(x, ea, u, bt);

    dim3 g1(HIDDEN / BN, (N_NODES + BM - 1) / BM);
    k_gemm<true><<<g1, 256, smem>>>(pH, pW1, b1, nullptr, pHid,
                                    N_NODES, MLP_IN, HIDDEN);
    dim3 g2(NODE_F / BN, (N_NODES + BM - 1) / BM);
    k_gemm<false><<<g2, 256, smem>>>(pHid, pW2, b2, x, out,
                                     N_NODES, HIDDEN, NODE_F);
}

// round 5
// speedup vs baseline: 1.6845x; 1.6466x over previous
#include <cuda_runtime.h>
#include <cuda_fp16.h>
#include <cstdint>
#include <cstddef>

#define N_NODES 50000
#define N_EDGES 800000
#define EDGE_F 96
#define NODE_F 256
#define GLOB_F 64
#define HIDDEN 1024
#define MLP_IN 608
#define CAP 128

// ---------------- scratch (static device globals; no allocations) ------------
__device__ int    g_cnt[N_NODES];
__device__ int    g_bucket[N_NODES * CAP];
__device__ __half g_h[(size_t)N_NODES * MLP_IN];     // fp16 MLP input
__device__ __half g_hid[(size_t)N_NODES * HIDDEN];   // fp16 hidden
__device__ __half g_w1t[HIDDEN * MLP_IN];            // W1^T fp16  [n][k]
__device__ __half g_w2t[NODE_F * HIDDEN];            // W2^T fp16  [n][k]

// ---------------- prep kernels ----------------------------------------------
__global__ void k_zero() {
    int i = blockIdx.x * blockDim.x + threadIdx.x;
    if (i < N_NODES) g_cnt[i] = 0;
}

__global__ void k_scatter(const int* __restrict__ col) {
    int e = blockIdx.x * blockDim.x + threadIdx.x;
    if (e >= N_EDGES) return;
    int c = col[e];
    int p = atomicAdd(&g_cnt[c], 1);
    if (p < CAP) g_bucket[c * CAP + p] = e;
}

// transpose + fp16-round weights
__global__ void k_cvtw(const float* __restrict__ W1, const float* __restrict__ W2) {
    int i = blockIdx.x * blockDim.x + threadIdx.x;
    const int n1 = HIDDEN * MLP_IN;
    const int nt = n1 + NODE_F * HIDDEN;
    if (i < n1) {
        int n = i / MLP_IN, k = i % MLP_IN;
        g_w1t[i] = __float2half_rn(W1[(size_t)k * HIDDEN + n]);
    } else if (i < nt) {
        int j = i - n1;
        int n = j / HIDDEN, k = j % HIDDEN;
        g_w2t[j] = __float2half_rn(W2[(size_t)k * NODE_F + n]);
    }
}

// warp-per-node gather-reduce with 4-wide index prefetch; fp16 h row output
__global__ void k_gather(const float* __restrict__ x, const float* __restrict__ ea,
                         const float* __restrict__ u, const int* __restrict__ batch) {
    int node = blockIdx.x * 8 + (threadIdx.x >> 5);
    if (node >= N_NODES) return;
    int lane = threadIdx.x & 31;
    int deg = g_cnt[node];
    if (deg > CAP) deg = CAP;
    const float NEG = __int_as_float(0xff800000);
    float s0 = 0.f, s1 = 0.f, s2 = 0.f;
    float m0 = NEG, m1 = NEG, m2 = NEG;
    const int* bk = g_bucket + node * CAP;

    int j = 0;
    for (; j + 4 <= deg; j += 4) {
        int e0 = bk[j], e1 = bk[j + 1], e2 = bk[j + 2], e3 = bk[j + 3];
        const float* r0p = ea + (size_t)e0 * EDGE_F;
        const float* r1p = ea + (size_t)e1 * EDGE_F;
        const float* r2p = ea + (size_t)e2 * EDGE_F;
        const float* r3p = ea + (size_t)e3 * EDGE_F;
        float a0 = r0p[lane], a1 = r0p[lane + 32], a2 = r0p[lane + 64];
        float b0 = r1p[lane], b1 = r1p[lane + 32], b2 = r1p[lane + 64];
        float c0 = r2p[lane], c1 = r2p[lane + 32], c2 = r2p[lane + 64];
        float d0 = r3p[lane], d1 = r3p[lane + 32], d2 = r3p[lane + 64];
        s0 += a0 + b0 + c0 + d0;
        s1 += a1 + b1 + c1 + d1;
        s2 += a2 + b2 + c2 + d2;
        m0 = fmaxf(m0, fmaxf(fmaxf(a0, b0), fmaxf(c0, d0)));
        m1 = fmaxf(m1, fmaxf(fmaxf(a1, b1), fmaxf(c1, d1)));
        m2 = fmaxf(m2, fmaxf(fmaxf(a2, b2), fmaxf(c2, d2)));
    }
    for (; j < deg; j++) {
        const float* r = ea + (size_t)bk[j] * EDGE_F;
        float v0 = r[lane], v1 = r[lane + 32], v2 = r[lane + 64];
        s0 += v0; m0 = fmaxf(m0, v0);
        s1 += v1; m1 = fmaxf(m1, v1);
        s2 += v2; m2 = fmaxf(m2, v2);
    }
    if (deg == 0) { m0 = 0.f; m1 = 0.f; m2 = 0.f; }
    float inv = deg ? 1.f / (float)deg : 0.f;

    __half* h = g_h + (size_t)node * MLP_IN;
    const float* xr = x + (size_t)node * NODE_F;
#pragma unroll
    for (int i = 0; i < 8; i++) h[lane + 32 * i] = __float2half_rn(xr[lane + 32 * i]);
    h[256 + lane] = __float2half_rn(s0);
    h[288 + lane] = __float2half_rn(s1);
    h[320 + lane] = __float2half_rn(s2);
    h[352 + lane] = __float2half_rn(m0);
    h[384 + lane] = __float2half_rn(m1);
    h[416 + lane] = __float2half_rn(m2);
    h[448 + lane] = __float2half_rn(s0 * inv);
    h[480 + lane] = __float2half_rn(s1 * inv);
    h[512 + lane] = __float2half_rn(s2 * inv);
    int g = batch[node];
    h[544 + lane] = __float2half_rn(u[g * GLOB_F + lane]);
    h[576 + lane] = __float2half_rn(u[g * GLOB_F + 32 + lane]);
}

// ---------------- fp16 GEMM (mma.sync m16n8k16 + ldmatrix, cp.async) ---------
// BM=BN=128, BK=32. smem rows: 32 halfs (64B) padded to 80B stride.
#define BM 128
#define BN 128
#define BK 32
#define ROWB 80
#define TILE_B (BM * ROWB)          // 10240 B per operand tile
#define STAGE_B (2 * TILE_B)        // 20480 B per stage

__device__ __forceinline__ void cp16(uint32_t dst, const void* src, int sz) {
    asm volatile("cp.async.cg.shared.global [%0], [%1], 16, %2;\n"
                 :: "r"(dst), "l"(src), "r"(sz));
}

__device__ __forceinline__ void ldsm4(uint32_t* r, uint32_t addr) {
    asm volatile("ldmatrix.sync.aligned.m8n8.x4.shared.b16 {%0,%1,%2,%3}, [%4];"
                 : "=r"(r[0]), "=r"(r[1]), "=r"(r[2]), "=r"(r[3]) : "r"(addr));
}

template <bool FIRST>
__global__ void __launch_bounds__(256, 2)
k_gemm(const __half* __restrict__ A, const __half* __restrict__ Bw,
       const float* __restrict__ bias, const float* __restrict__ resid,
       void* __restrict__ Cp, int M, int K, int N) {
    extern __shared__ char smc[];
    uint32_t smb = (uint32_t)__cvta_generic_to_shared(smc);
    int tid = threadIdx.x;
    int warp = tid >> 5, lane = tid & 31;
    int bm = blockIdx.y * BM;
    int bn = blockIdx.x * BN;
    int KT = K / BK;

    auto load = [&](int st, int kb) {
        uint32_t ab = smb + st * STAGE_B;
        uint32_t bb = ab + TILE_B;
#pragma unroll
        for (int i = 0; i < 2; i++) {
            int id = tid + i * 256;
            int r = id >> 2, c = id & 3;
            int gr = bm + r;
            const __half* srcA = A + (size_t)((gr < M) ? gr : 0) * K + kb * BK + c * 8;
            cp16(ab + r * ROWB + c * 16, srcA, (gr < M) ? 16 : 0);
            const __half* srcB = Bw + (size_t)(bn + r) * K + kb * BK + c * 8;
            cp16(bb + r * ROWB + c * 16, srcB, 16);
        }
    };

    load(0, 0);
    asm volatile("cp.async.commit_group;\n");

    float acc[4][4][4];
#pragma unroll
    for (int a = 0; a < 4; a++)
#pragma unroll
        for (int b = 0; b < 4; b++)
#pragma unroll
            for (int c = 0; c < 4; c++) acc[a][b][c] = 0.f;

    int wm = (warp & 1) * 64, wn = (warp >> 1) * 32;
    // ldmatrix lane address components
    int a_m = (lane & 7) + ((lane >> 3) & 1) * 8;   // m offset within m16
    int a_k8 = (lane >> 4) * 8;                     // k offset (0 or 8) within k16
    int b_n = lane & 7;                             // n offset within n8
    int b_k8 = (lane >> 3) * 8;                     // k chunk 0,8,16,24

    for (int kt = 0; kt < KT; kt++) {
        if (kt + 1 < KT) load((kt + 1) & 1, kt + 1);
        asm volatile("cp.async.commit_group;\n");
        asm volatile("cp.async.wait_group 1;\n");
        __syncthreads();
        uint32_t ab = smb + (kt & 1) * STAGE_B;
        uint32_t bb = ab + TILE_B;

        uint32_t bF[4][4];
#pragma unroll
        for (int nt = 0; nt < 4; nt++)
            ldsm4(bF[nt], bb + (wn + nt * 8 + b_n) * ROWB + b_k8 * 2);

#pragma unroll
        for (int ks = 0; ks < 2; ks++) {
            uint32_t aF[4][4];
#pragma unroll
            for (int mt = 0; mt < 4; mt++)
                ldsm4(aF[mt], ab + (wm + mt * 16 + a_m) * ROWB + (ks * 16 + a_k8) * 2);
#pragma unroll
            for (int mt = 0; mt < 4; mt++)
#pragma unroll
                for (int nt = 0; nt < 4; nt++)
                    asm volatile(
                        "mma.sync.aligned.m16n8k16.row.col.f32.f16.f16.f32 "
                        "{%0,%1,%2,%3},{%4,%5,%6,%7},{%8,%9},{%0,%1,%2,%3};\n"
                        : "+f"(acc[mt][nt][0]), "+f"(acc[mt][nt][1]),
                          "+f"(acc[mt][nt][2]), "+f"(acc[mt][nt][3])
                        : "r"(aF[mt][0]), "r"(aF[mt][1]), "r"(aF[mt][2]), "r"(aF[mt][3]),
                          "r"(bF[nt][2 * ks]), "r"(bF[nt][2 * ks + 1]));
        }
        __syncthreads();
    }

    // ---------------- epilogue ----------------
    int lr = lane >> 2, lc = lane & 3;
#pragma unroll
    for (int mt = 0; mt < 4; mt++) {
        int rb = bm + wm + mt * 16 + lr;
#pragma unroll
        for (int nt = 0; nt < 4; nt++) {
            int cb = bn + wn + nt * 8 + 2 * lc;
            float bx = bias[cb], by = bias[cb + 1];
            int row0 = rb, row1 = rb + 8;
            if (FIRST) {
                __half* C = (__half*)Cp;
                if (row0 < M) {
                    float v0 = fmaxf(acc[mt][nt][0] + bx, 0.f);
                    float v1 = fmaxf(acc[mt][nt][1] + by, 0.f);
                    *(__half2*)(C + (size_t)row0 * N + cb) = __floats2half2_rn(v0, v1);
                }
                if (row1 < M) {
                    float v2 = fmaxf(acc[mt][nt][2] + bx, 0.f);
                    float v3 = fmaxf(acc[mt][nt][3] + by, 0.f);
                    *(__half2*)(C + (size_t)row1 * N + cb) = __floats2half2_rn(v2, v3);
                }
            } else {
                float* C = (float*)Cp;
                if (row0 < M) {
                    C[(size_t)row0 * N + cb]     = acc[mt][nt][0] + bx + resid[(size_t)row0 * N + cb];
                    C[(size_t)row0 * N + cb + 1] = acc[mt][nt][1] + by + resid[(size_t)row0 * N + cb + 1];
                }
                if (row1 < M) {
                    C[(size_t)row1 * N + cb]     = acc[mt][nt][2] + bx + resid[(size_t)row1 * N + cb];
                    C[(size_t)row1 * N + cb + 1] = acc[mt][nt][3] + by + resid[(size_t)row1 * N + cb + 1];
                }
            }
        }
    }
}

// ---------------- launch ------------------------------------------------------
extern "C" void kernel_launch(void* const* d_in, const int* in_sizes, int n_in,
                              void* d_out, int out_size) {
    const float* x  = (const float*)d_in[0];
    const float* ea = (const float*)d_in[1];
    const float* u  = (const float*)d_in[2];
    const float* W1 = (const float*)d_in[3];
    const float* b1 = (const float*)d_in[4];
    const float* W2 = (const float*)d_in[5];
    const float* b2 = (const float*)d_in[6];
    const int*   ei = (const int*)d_in[7];   // [2, N_EDGES] int32
    const int*   bt = (const int*)d_in[8];
    float* out = (float*)d_out;

    __half *pH, *pHid, *pW1t, *pW2t;
    cudaGetSymbolAddress((void**)&pH, g_h);
    cudaGetSymbolAddress((void**)&pHid, g_hid);
    cudaGetSymbolAddress((void**)&pW1t, g_w1t);
    cudaGetSymbolAddress((void**)&pW2t, g_w2t);

    const int smem = 2 * STAGE_B;   // 40960 B
    cudaFuncSetAttribute(k_gemm<true>,  cudaFuncAttributeMaxDynamicSharedMemorySize, smem);
    cudaFuncSetAttribute(k_gemm<false>, cudaFuncAttributeMaxDynamicSharedMemorySize, smem);

    k_zero<<<(N_NODES + 255) / 256, 256>>>();
    k_scatter<<<(N_EDGES + 255) / 256, 256>>>(ei + N_EDGES);
    k_cvtw<<<(HIDDEN * MLP_IN + NODE_F * HIDDEN + 255) / 256, 256>>>(W1, W2);
    k_gather<<<(N_NODES + 7) / 8, 256>>>(x, ea, u, bt);

    dim3 g1(HIDDEN / BN, (N_NODES + BM - 1) / BM);   // (8, 391)
    k_gemm<true><<<g1, 256, smem>>>(pH, pW1t, b1, nullptr, (void*)pHid,
                                    N_NODES, MLP_IN, HIDDEN);
    dim3 g2(NODE_F / BN, (N_NODES + BM - 1) / BM);   // (2, 391)
    k_gemm<false><<<g2, 256, smem>>>(pHid, pW2t, b2, x, (void*)out,
                                     N_NODES, HIDDEN, NODE_F);
}